// round 8
// baseline (speedup 1.0000x reference)
#include <cuda_runtime.h>
#include <cuda_bf16.h>
#include <math.h>

// ---------------- problem constants ----------------
#define NN 30000
#define NE 480000
#define HD 128
#define NLAYERS 4
#define NGRAPH 32
#define NOUT 12
#define IN_NODE 64
#define IN_EDGE 16
#define EPS_BN 1e-5f
#define EPS_STD 1e-5f
#define AVG_LOG 1.3821454785306007f
#define AGG_COLS (4 * HD)   // 512
#define KPOST (13 * HD)     // 1664

// ---------------- scratch (static device globals; no allocation) ----------------
__device__ float g_h   [NN * HD];             // node features
__device__ float g_A   [NN * HD];             // h @ preW[0:H]   (dst part)
__device__ float g_B   [NN * HD];             // h @ preW[H:2H]  (src part)
__device__ float g_ea2 [(size_t)NE * IN_EDGE];// edge_attr permuted to CSR order
__device__ int   g_src2[NE];                  // src permuted to CSR order
__device__ float g_agg [(size_t)NN * AGG_COLS]; // [mean|min|max|std] raw
__device__ float g_amp [NN];
__device__ float g_iamp[NN];
__device__ float g_t   [NN * HD];             // post+lin output (pre-BN)
__device__ int   g_deg [NN];
__device__ int   g_rowptr[NN + 1];
__device__ int   g_cursor[NN];
__device__ int   g_csr [NE];
__device__ float g_Wec [HD * HD];             // encW @ preW[2H:3H]
__device__ float g_becT[HD];                  // encB@preW2 + preB
__device__ float g_Wf  [IN_EDGE * HD];        // eWm @ Wec   (K=16 edge weight)
__device__ float g_bf  [HD];                  // ebv@Wec + becT
__device__ float g_Wol [KPOST * HD];          // post_W @ lin_W  [1664,128]
__device__ float g_bol [HD];
__device__ float g_bn  [2 * HD];              // column sums / sumsq for BN
__device__ float g_pool[NGRAPH * HD];

// ---------------- generic fp32 GEMM: C[M,128] = A[M,K] @ W[K,128] (+bias) ----------------
// Tile 128x128x16, 256 threads, 8x8 per thread (cols tc*4..+3 and 64+tc*4..+3).
// K must be a multiple of 16.
#define GBM 128
#define GBN 128
#define GBK 16

__global__ void __launch_bounds__(256)
gemm128(const float* __restrict__ A, const float* __restrict__ W,
        const float* __restrict__ bias, float* __restrict__ C,
        int M, int K) {
    __shared__ float sA[GBK][GBM];
    __shared__ float sW[GBK][GBN];
    const int tid = threadIdx.x;
    const int tr = tid >> 4;        // 0..15 (row group)
    const int tc = tid & 15;        // 0..15 (col group)
    const int bm0 = blockIdx.x * GBM;

    float acc[8][8];
#pragma unroll
    for (int i = 0; i < 8; i++)
#pragma unroll
        for (int j = 0; j < 8; j++) acc[i][j] = 0.f;

    const int ar = tid >> 1;            // A tile row (0..127)
    const int ak = (tid & 1) * 8;       // A tile k offset 0/8
    const int wr = tid >> 4;            // W tile row (0..15)
    const int wc = (tid & 15) * 8;      // W tile col (0..120)

    for (int k0 = 0; k0 < K; k0 += GBK) {
        float4 a0 = make_float4(0.f, 0.f, 0.f, 0.f), a1 = a0;
        int arow = bm0 + ar;
        if (arow < M) {
            const float* ap = &A[(size_t)arow * K + k0 + ak];
            a0 = *reinterpret_cast<const float4*>(ap);
            a1 = *reinterpret_cast<const float4*>(ap + 4);
        }
        sA[ak + 0][ar] = a0.x; sA[ak + 1][ar] = a0.y;
        sA[ak + 2][ar] = a0.z; sA[ak + 3][ar] = a0.w;
        sA[ak + 4][ar] = a1.x; sA[ak + 5][ar] = a1.y;
        sA[ak + 6][ar] = a1.z; sA[ak + 7][ar] = a1.w;
        const float* wp = &W[(size_t)(k0 + wr) * GBN + wc];
        *reinterpret_cast<float4*>(&sW[wr][wc])     = *reinterpret_cast<const float4*>(wp);
        *reinterpret_cast<float4*>(&sW[wr][wc + 4]) = *reinterpret_cast<const float4*>(wp + 4);
        __syncthreads();
#pragma unroll
        for (int k = 0; k < GBK; k++) {
            float4 ra0 = *reinterpret_cast<const float4*>(&sA[k][tr * 8]);
            float4 ra1 = *reinterpret_cast<const float4*>(&sA[k][tr * 8 + 4]);
            float4 rw0 = *reinterpret_cast<const float4*>(&sW[k][tc * 4]);
            float4 rw1 = *reinterpret_cast<const float4*>(&sW[k][64 + tc * 4]);
            float ra[8] = {ra0.x, ra0.y, ra0.z, ra0.w, ra1.x, ra1.y, ra1.z, ra1.w};
            float rw[8] = {rw0.x, rw0.y, rw0.z, rw0.w, rw1.x, rw1.y, rw1.z, rw1.w};
#pragma unroll
            for (int m = 0; m < 8; m++)
#pragma unroll
                for (int n = 0; n < 8; n++) acc[m][n] += ra[m] * rw[n];
        }
        __syncthreads();
    }

    float4 bv0 = make_float4(0.f, 0.f, 0.f, 0.f), bv1 = bv0;
    if (bias) {
        bv0 = *reinterpret_cast<const float4*>(&bias[tc * 4]);
        bv1 = *reinterpret_cast<const float4*>(&bias[64 + tc * 4]);
    }
#pragma unroll
    for (int m = 0; m < 8; m++) {
        int row = bm0 + tr * 8 + m;
        if (row < M) {
            float4 v0 = make_float4(acc[m][0] + bv0.x, acc[m][1] + bv0.y,
                                    acc[m][2] + bv0.z, acc[m][3] + bv0.w);
            float4 v1 = make_float4(acc[m][4] + bv1.x, acc[m][5] + bv1.y,
                                    acc[m][6] + bv1.z, acc[m][7] + bv1.w);
            *reinterpret_cast<float4*>(&C[(size_t)row * GBN + tc * 4]) = v0;
            *reinterpret_cast<float4*>(&C[(size_t)row * GBN + 64 + tc * 4]) = v1;
        }
    }
}

// ---------------- post-NN GEMM with virtual A = [h|agg|amp*agg|iamp*agg] ----------------
// t = virtA @ Wol + bol, K = 1664. Also accumulates BN column sums/sumsq
// into g_bn via a smem reduction (g_bn must be zeroed beforehand).
__global__ void __launch_bounds__(256)
gemm_post() {
    __shared__ float sA[GBK][GBM];
    __shared__ float sW[GBK][GBN];
    __shared__ float red[2][16][GBM];
    const int tid = threadIdx.x;
    const int tr = tid >> 4;
    const int tc = tid & 15;
    const int bm0 = blockIdx.x * GBM;

    float acc[8][8];
#pragma unroll
    for (int i = 0; i < 8; i++)
#pragma unroll
        for (int j = 0; j < 8; j++) acc[i][j] = 0.f;

    const int ar = tid >> 1;
    const int ak = (tid & 1) * 8;
    const int wr = tid >> 4;
    const int wc = (tid & 15) * 8;

    const int arow = bm0 + ar;
    const bool rowok = arow < NN;
    const float ampv  = rowok ? g_amp[arow]  : 0.f;
    const float iampv = rowok ? g_iamp[arow] : 0.f;
    const float* hrow = &g_h[(size_t)arow * HD];
    const float* arow_p = &g_agg[(size_t)arow * AGG_COLS];

    for (int k0 = 0; k0 < KPOST; k0 += GBK) {
        float4 a0 = make_float4(0.f, 0.f, 0.f, 0.f), a1 = a0;
        if (rowok) {
            const float* src;
            float scale = 1.f;
            if (k0 < HD) {
                src = hrow + k0 + ak;
            } else {
                int kk = k0 - HD;
                int region = kk / AGG_COLS;          // 0,1,2 (uniform per tile)
                src = arow_p + (kk - region * AGG_COLS) + ak;
                scale = (region == 0) ? 1.f : ((region == 1) ? ampv : iampv);
            }
            a0 = *reinterpret_cast<const float4*>(src);
            a1 = *reinterpret_cast<const float4*>(src + 4);
            a0.x *= scale; a0.y *= scale; a0.z *= scale; a0.w *= scale;
            a1.x *= scale; a1.y *= scale; a1.z *= scale; a1.w *= scale;
        }
        sA[ak + 0][ar] = a0.x; sA[ak + 1][ar] = a0.y;
        sA[ak + 2][ar] = a0.z; sA[ak + 3][ar] = a0.w;
        sA[ak + 4][ar] = a1.x; sA[ak + 5][ar] = a1.y;
        sA[ak + 6][ar] = a1.z; sA[ak + 7][ar] = a1.w;
        const float* wp = &g_Wol[(size_t)(k0 + wr) * GBN + wc];
        *reinterpret_cast<float4*>(&sW[wr][wc])     = *reinterpret_cast<const float4*>(wp);
        *reinterpret_cast<float4*>(&sW[wr][wc + 4]) = *reinterpret_cast<const float4*>(wp + 4);
        __syncthreads();
#pragma unroll
        for (int k = 0; k < GBK; k++) {
            float4 ra0 = *reinterpret_cast<const float4*>(&sA[k][tr * 8]);
            float4 ra1 = *reinterpret_cast<const float4*>(&sA[k][tr * 8 + 4]);
            float4 rw0 = *reinterpret_cast<const float4*>(&sW[k][tc * 4]);
            float4 rw1 = *reinterpret_cast<const float4*>(&sW[k][64 + tc * 4]);
            float ra[8] = {ra0.x, ra0.y, ra0.z, ra0.w, ra1.x, ra1.y, ra1.z, ra1.w};
            float rw[8] = {rw0.x, rw0.y, rw0.z, rw0.w, rw1.x, rw1.y, rw1.z, rw1.w};
#pragma unroll
            for (int m = 0; m < 8; m++)
#pragma unroll
                for (int n = 0; n < 8; n++) acc[m][n] += ra[m] * rw[n];
        }
        __syncthreads();
    }

    float4 bv0 = *reinterpret_cast<const float4*>(&g_bol[tc * 4]);
    float4 bv1 = *reinterpret_cast<const float4*>(&g_bol[64 + tc * 4]);
    float colsum[8] = {0,0,0,0,0,0,0,0};
    float colsq [8] = {0,0,0,0,0,0,0,0};
#pragma unroll
    for (int m = 0; m < 8; m++) {
        int row = bm0 + tr * 8 + m;
        if (row < NN) {
            float v[8];
            v[0] = acc[m][0] + bv0.x; v[1] = acc[m][1] + bv0.y;
            v[2] = acc[m][2] + bv0.z; v[3] = acc[m][3] + bv0.w;
            v[4] = acc[m][4] + bv1.x; v[5] = acc[m][5] + bv1.y;
            v[6] = acc[m][6] + bv1.z; v[7] = acc[m][7] + bv1.w;
            *reinterpret_cast<float4*>(&g_t[(size_t)row * HD + tc * 4]) =
                make_float4(v[0], v[1], v[2], v[3]);
            *reinterpret_cast<float4*>(&g_t[(size_t)row * HD + 64 + tc * 4]) =
                make_float4(v[4], v[5], v[6], v[7]);
#pragma unroll
            for (int n = 0; n < 8; n++) { colsum[n] += v[n]; colsq[n] += v[n] * v[n]; }
        }
    }
    // BN partial reduction: red[s][tr][col]
#pragma unroll
    for (int n = 0; n < 4; n++) {
        red[0][tr][tc * 4 + n]      = colsum[n];
        red[0][tr][64 + tc * 4 + n] = colsum[4 + n];
        red[1][tr][tc * 4 + n]      = colsq[n];
        red[1][tr][64 + tc * 4 + n] = colsq[4 + n];
    }
    __syncthreads();
    if (tid < GBM) {
        float s = 0.f, q = 0.f;
#pragma unroll
        for (int r = 0; r < 16; r++) { s += red[0][r][tid]; q += red[1][r][tid]; }
        atomicAdd(&g_bn[tid], s);
        atomicAdd(&g_bn[HD + tid], q);
    }
}

// ---------------- CSR construction ----------------
__global__ void deg_kernel(const int* __restrict__ dst) {
    int e = blockIdx.x * 256 + threadIdx.x;
    if (e < NE) atomicAdd(&g_deg[dst[e]], 1);
}

__global__ void scan_kernel() {           // single block, 1024 threads
    __shared__ int part[1024];
    const int t = threadIdx.x;
    const int C = (NN + 1023) / 1024;     // 30
    int s = 0;
    for (int j = 0; j < C; j++) {
        int i = t * C + j;
        if (i < NN) s += g_deg[i];
    }
    part[t] = s;
    __syncthreads();
    for (int off = 1; off < 1024; off <<= 1) {
        int v = (t >= off) ? part[t - off] : 0;
        __syncthreads();
        part[t] += v;
        __syncthreads();
    }
    int base = t ? part[t - 1] : 0;
    for (int j = 0; j < C; j++) {
        int i = t * C + j;
        if (i < NN) { g_rowptr[i] = base; g_cursor[i] = base; base += g_deg[i]; }
    }
    if (t == 0) g_rowptr[NN] = NE;
}

__global__ void scatter_kernel(const int* __restrict__ dst) {
    int e = blockIdx.x * 256 + threadIdx.x;
    if (e < NE) {
        int p = atomicAdd(&g_cursor[dst[e]], 1);
        g_csr[p] = e;
    }
}

// permute edge_attr (4 x float4 per edge) and src into CSR order
__global__ void permute_kernel(const float* __restrict__ ea,
                               const int* __restrict__ src) {
    int idx = blockIdx.x * 256 + threadIdx.x;   // NE*4 threads
    if (idx < NE * 4) {
        int p = idx >> 2, q = idx & 3;
        int e = g_csr[p];
        reinterpret_cast<float4*>(g_ea2)[p * 4 + q] =
            reinterpret_cast<const float4*>(ea)[e * 4 + q];
        if (q == 0) g_src2[p] = src[e];
    }
}

// ---------------- fold helpers ----------------
__global__ void fold_bias(const float* __restrict__ bv, const float* __restrict__ W,
                          const float* __restrict__ badd, float* __restrict__ out) {
    int c = threadIdx.x;
    float s = badd[c];
    for (int k = 0; k < HD; k++) s += bv[k] * W[k * HD + c];
    out[c] = s;
}

// ---------------- fused edge-message + aggregation ----------------
// One block per node (128 threads, one column each). Thread c keeps Wf[:,c]
// in registers; per CSR edge it recomputes m_c = ea2[p]·Wf[:,c] + B[src][c]
// + bf[c] on the fly and reduces sum/sq/min/max in registers. Unrolled by 2
// edges with loads hoisted ahead of both FMA chains (MLP=2).
__global__ void __launch_bounds__(128)
agg_fused() {
    const int i = blockIdx.x;     // node
    const int c = threadIdx.x;    // column
    const int beg = g_rowptr[i];
    const int end = g_rowptr[i + 1];
    const int deg = end - beg;

    float wf[IN_EDGE];
#pragma unroll
    for (int k = 0; k < IN_EDGE; k++) wf[k] = g_Wf[k * HD + c];   // coalesced
    const float bfc = g_bf[c];
    const float a = g_A[(size_t)i * HD + c];

    float sum = 0.f, sq = 0.f;
    float mn = 3.4e38f, mx = -3.4e38f;
    int p = beg;
    for (; p + 1 < end; p += 2) {
        // hoist all loads for both edges before either FMA chain
        int s0 = g_src2[p];
        int s1 = g_src2[p + 1];
        const float4* ea0 = reinterpret_cast<const float4*>(&g_ea2[(size_t)p * IN_EDGE]);
        const float4* ea1 = reinterpret_cast<const float4*>(&g_ea2[(size_t)(p + 1) * IN_EDGE]);
        float4 x0 = ea0[0], x1 = ea0[1], x2 = ea0[2], x3 = ea0[3];
        float4 y0 = ea1[0], y1 = ea1[1], y2 = ea1[2], y3 = ea1[3];
        float b0 = g_B[(size_t)s0 * HD + c];
        float b1 = g_B[(size_t)s1 * HD + c];

        float v0 = bfc + b0;
        v0 += x0.x * wf[0]  + x0.y * wf[1]  + x0.z * wf[2]  + x0.w * wf[3];
        v0 += x1.x * wf[4]  + x1.y * wf[5]  + x1.z * wf[6]  + x1.w * wf[7];
        v0 += x2.x * wf[8]  + x2.y * wf[9]  + x2.z * wf[10] + x2.w * wf[11];
        v0 += x3.x * wf[12] + x3.y * wf[13] + x3.z * wf[14] + x3.w * wf[15];

        float v1 = bfc + b1;
        v1 += y0.x * wf[0]  + y0.y * wf[1]  + y0.z * wf[2]  + y0.w * wf[3];
        v1 += y1.x * wf[4]  + y1.y * wf[5]  + y1.z * wf[6]  + y1.w * wf[7];
        v1 += y2.x * wf[8]  + y2.y * wf[9]  + y2.z * wf[10] + y2.w * wf[11];
        v1 += y3.x * wf[12] + y3.y * wf[13] + y3.z * wf[14] + y3.w * wf[15];

        sum += v0 + v1;
        sq  += v0 * v0 + v1 * v1;
        mn = fminf(mn, fminf(v0, v1));
        mx = fmaxf(mx, fmaxf(v0, v1));
    }
    if (p < end) {
        const float4* ear = reinterpret_cast<const float4*>(&g_ea2[(size_t)p * IN_EDGE]);
        float4 e0 = ear[0], e1 = ear[1], e2 = ear[2], e3 = ear[3];
        int s = g_src2[p];
        float v = bfc + g_B[(size_t)s * HD + c];
        v += e0.x * wf[0]  + e0.y * wf[1]  + e0.z * wf[2]  + e0.w * wf[3];
        v += e1.x * wf[4]  + e1.y * wf[5]  + e1.z * wf[6]  + e1.w * wf[7];
        v += e2.x * wf[8]  + e2.y * wf[9]  + e2.z * wf[10] + e2.w * wf[11];
        v += e3.x * wf[12] + e3.y * wf[13] + e3.z * wf[14] + e3.w * wf[15];
        sum += v; sq += v * v;
        mn = fminf(mn, v); mx = fmaxf(mx, v);
    }

    float mean, mnv, mxv, stdv;
    float fd = (float)deg;
    float degc = fmaxf(fd, 1.f);
    if (deg == 0) {
        mean = 0.f; mnv = 0.f; mxv = 0.f; stdv = sqrtf(EPS_STD);
    } else {
        float inv = 1.f / fd;
        float sum_m = sum + fd * a;        // fold constant A[dst] back in
        mean = sum_m * inv;
        float sq_m = sq + 2.f * a * sum + fd * a * a;
        float msq = sq_m * inv;
        stdv = sqrtf(fmaxf(msq - mean * mean, 0.f) + EPS_STD);
        mnv = mn + a;
        mxv = mx + a;
    }

    float* row = &g_agg[(size_t)i * AGG_COLS];
    row[c]          = mean;
    row[HD + c]     = mnv;
    row[2 * HD + c] = mxv;
    row[3 * HD + c] = stdv;
    if (c == 0) {
        float amp = logf(degc + 1.f) * (1.f / AVG_LOG);
        g_amp[i] = amp;
        g_iamp[i] = 1.f / amp;
    }
}

// ---------------- batchnorm apply + relu ----------------
__global__ void bn_apply(const float* __restrict__ srcbuf,
                         const float* __restrict__ gamma,
                         const float* __restrict__ beta) {
    int idx = blockIdx.x * 256 + threadIdx.x;   // NN*HD divisible by 256
    int c = idx & (HD - 1);
    float mu = g_bn[c] * (1.f / NN);
    float var = g_bn[HD + c] * (1.f / NN) - mu * mu;
    float sc = gamma[c] * rsqrtf(var + EPS_BN);
    float v = (srcbuf[idx] - mu) * sc + beta[c];
    g_h[idx] = fmaxf(v, 0.f);
}

// ---------------- pool + head ----------------
__global__ void pool_kernel(const int* __restrict__ batch) {
    int i = blockIdx.x;
    int c = threadIdx.x;
    atomicAdd(&g_pool[batch[i] * HD + c], g_h[(size_t)i * HD + c]);
}

__global__ void head_kernel(const float* __restrict__ W1, const float* __restrict__ b1,
                            const float* __restrict__ W2, const float* __restrict__ b2,
                            float* __restrict__ out) {
    int g = blockIdx.x;         // 32 graphs
    int t = threadIdx.x;        // 64 threads
    __shared__ float z[64];
    float s = b1[t];
    for (int k = 0; k < HD; k++) s += g_pool[g * HD + k] * W1[k * 64 + t];
    z[t] = fmaxf(s, 0.f);
    __syncthreads();
    if (t < NOUT) {
        float o = b2[t];
        for (int k = 0; k < 64; k++) o += z[k] * W2[k * NOUT + t];
        out[g * NOUT + t] = o;
    }
}

// ---------------- launch ----------------
extern "C" void kernel_launch(void* const* d_in, const int* in_sizes, int n_in,
                              void* d_out, int out_size) {
    (void)n_in; (void)out_size;
    // First four tensors may arrive in signature order (x, edge_index, batch,
    // edge_attr) or dict order (x, edge_attr, edge_index, batch). Element
    // counts are pairwise distinct -> detect at runtime.
    int ix = 0, iei = 1, ib = 2, iea = 3;
    for (int i = 0; i < 4; i++) {
        switch (in_sizes[i]) {
            case NN * IN_NODE: ix  = i; break;   // 1,920,000
            case 2 * NE:       iei = i; break;   //   960,000
            case NN:           ib  = i; break;   //    30,000
            case NE * IN_EDGE: iea = i; break;   // 7,680,000
            default: break;
        }
    }
    const float* x     = (const float*)d_in[ix];
    const int*   eidx  = (const int*)  d_in[iei];
    const int*   batch = (const int*)  d_in[ib];
    const float* ea    = (const float*)d_in[iea];
    const float* nW    = (const float*)d_in[4];
    const float* nb    = (const float*)d_in[5];
    const float* eWm   = (const float*)d_in[6];
    const float* ebv   = (const float*)d_in[7];
    const float* encW  = (const float*)d_in[8];
    const float* encB  = (const float*)d_in[9];
    const float* preW  = (const float*)d_in[10];
    const float* preB  = (const float*)d_in[11];
    const float* postW = (const float*)d_in[12];
    const float* postB = (const float*)d_in[13];
    const float* linW  = (const float*)d_in[14];
    const float* linB  = (const float*)d_in[15];
    const float* bnG   = (const float*)d_in[16];
    const float* bnB   = (const float*)d_in[17];
    const float* h1W   = (const float*)d_in[18];
    const float* h1b   = (const float*)d_in[19];
    const float* h2W   = (const float*)d_in[20];
    const float* h2b   = (const float*)d_in[21];
    float* out = (float*)d_out;

    const int* srcp = eidx;        // edge_index[0]
    const int* dstp = eidx + NE;   // edge_index[1]

    void *p_h, *p_A, *p_B, *p_t, *p_deg, *p_Wec, *p_becT, *p_Wf, *p_bf,
         *p_Wol, *p_bol, *p_bn, *p_pool;
    cudaGetSymbolAddress(&p_h, g_h);
    cudaGetSymbolAddress(&p_A, g_A);
    cudaGetSymbolAddress(&p_B, g_B);
    cudaGetSymbolAddress(&p_t, g_t);
    cudaGetSymbolAddress(&p_deg, g_deg);
    cudaGetSymbolAddress(&p_Wec, g_Wec);
    cudaGetSymbolAddress(&p_becT, g_becT);
    cudaGetSymbolAddress(&p_Wf, g_Wf);
    cudaGetSymbolAddress(&p_bf, g_bf);
    cudaGetSymbolAddress(&p_Wol, g_Wol);
    cudaGetSymbolAddress(&p_bol, g_bol);
    cudaGetSymbolAddress(&p_bn, g_bn);
    cudaGetSymbolAddress(&p_pool, g_pool);

    // ---- CSR build (edge_index constant; rebuilt each replay, cheap) ----
    cudaMemsetAsync(p_deg, 0, NN * sizeof(int));
    deg_kernel<<<(NE + 255) / 256, 256>>>(dstp);
    scan_kernel<<<1, 1024>>>();
    scatter_kernel<<<(NE + 255) / 256, 256>>>(dstp);
    permute_kernel<<<(NE * 4 + 255) / 256, 256>>>(ea, srcp);

    // ---- node embedding ----
    gemm128<<<(NN + GBM - 1) / GBM, 256>>>(x, nW, nb, (float*)p_h, NN, IN_NODE);

    for (int l = 0; l < NLAYERS; l++) {
        const float* preWl  = preW  + (size_t)l * 3 * HD * HD;
        const float* postWl = postW + (size_t)l * KPOST * HD;
        const float* linWl  = linW  + (size_t)l * HD * HD;

        // Wec = encW @ preW[2H:3H];  becT = encB@preW2 + preB
        gemm128<<<1, 256>>>(encW + (size_t)l * HD * HD, preWl + 2 * HD * HD,
                            nullptr, (float*)p_Wec, HD, HD);
        fold_bias<<<1, HD>>>(encB + l * HD, preWl + 2 * HD * HD, preB + l * HD,
                             (float*)p_becT);
        // Wf = eWm @ Wec (K=16 edge weight);  bf = ebv@Wec + becT
        gemm128<<<1, 256>>>(eWm, (const float*)p_Wec, nullptr, (float*)p_Wf,
                            IN_EDGE, HD);
        fold_bias<<<1, HD>>>(ebv, (const float*)p_Wec, (const float*)p_becT,
                             (float*)p_bf);
        // Wol = postW @ linW;  bol = postB@linW + linB
        gemm128<<<13, 256>>>(postWl, linWl, nullptr, (float*)p_Wol, KPOST, HD);
        fold_bias<<<1, HD>>>(postB + l * HD, linWl, linB + l * HD, (float*)p_bol);

        // node-side pre-NN parts
        gemm128<<<(NN + GBM - 1) / GBM, 256>>>((const float*)p_h, preWl, nullptr,
                                               (float*)p_A, NN, HD);
        gemm128<<<(NN + GBM - 1) / GBM, 256>>>((const float*)p_h, preWl + HD * HD,
                                               nullptr, (float*)p_B, NN, HD);

        // fused edge-message recompute + aggregation -> g_agg, amp, iamp
        agg_fused<<<NN, HD>>>();

        // post-NN + lin via virtual-A GEMM; also accumulates BN stats
        cudaMemsetAsync(p_bn, 0, 2 * HD * 4);
        gemm_post<<<(NN + GBM - 1) / GBM, 256>>>();

        // batchnorm normalize + relu -> g_h
        bn_apply<<<(NN * HD) / 256, 256>>>((const float*)p_t, bnG + l * HD,
                                           bnB + l * HD);
    }

    // global add pool + MLP head
    cudaMemsetAsync(p_pool, 0, NGRAPH * HD * 4);
    pool_kernel<<<NN, HD>>>(batch);
    head_kernel<<<NGRAPH, 64>>>(h1W, h1b, h2W, h2b, out);
}

// round 12
// speedup vs baseline: 1.1241x; 1.1241x over previous
#include <cuda_runtime.h>
#include <cuda_bf16.h>
#include <math.h>

// ---------------- problem constants ----------------
#define NN 30000
#define NE 480000
#define HD 128
#define NLAYERS 4
#define NGRAPH 32
#define NOUT 12
#define IN_NODE 64
#define IN_EDGE 16
#define EPS_BN 1e-5f
#define EPS_STD 1e-5f
#define AVG_LOG 1.3821454785306007f
#define AGG_COLS 512        // [mean|min|max|std]
#define KPOST (13 * HD)     // 1664
#define NCAT 384            // W1|W2|W3 output columns

// ---------------- scratch (static device globals; no allocation) ----------------
__device__ float g_h   [NN * HD];              // node features
__device__ float g_A   [NN * HD];              // h @ preW[0:H]   (dst part)
__device__ float g_B   [NN * HD];              // h @ preW[H:2H]  (src part)
__device__ float g_ea2 [(size_t)NE * IN_EDGE]; // edge_attr permuted to CSR order
__device__ int   g_src2[NE];                   // src permuted to CSR order
__device__ __nv_bfloat16 g_aggh[(size_t)NN * AGG_COLS];  // agg hi
__device__ __nv_bfloat16 g_aggl[(size_t)NN * AGG_COLS];  // agg lo (residual)
__device__ float g_amp [NN];
__device__ float g_iamp[NN];
__device__ float g_V   [(size_t)NN * NCAT];    // agg @ [W1|W2|W3]
__device__ float g_t   [NN * HD];              // post+lin output (pre-BN)
__device__ int   g_deg [NN];
__device__ int   g_rowptr[NN + 1];
__device__ int   g_cursor[NN];
__device__ int   g_csr [NE];
__device__ float g_Wec [HD * HD];              // encW @ preW[2H:3H]
__device__ float g_becT[HD];                   // encB@preW2 + preB
__device__ float g_Wf  [IN_EDGE * HD];         // eWm @ Wec
__device__ float g_bf  [HD];                   // ebv@Wec + becT
__device__ float g_Wol [KPOST * HD];           // post_W @ lin_W  [1664,128]
__device__ float g_bol [HD];
__device__ __nv_bfloat16 g_Wch[(size_t)NCAT * AGG_COLS]; // Wcat hi, n-major [384][512]
__device__ __nv_bfloat16 g_Wcl[(size_t)NCAT * AGG_COLS]; // Wcat lo
__device__ float g_bn  [2 * HD];               // column sums / sumsq for BN
__device__ float g_pool[NGRAPH * HD];

// ---------------- generic fp32 GEMM: C[M,128] = A[M,K] @ W[K,128] (+bias) ----------------
#define GBM 128
#define GBN 128
#define GBK 16

__global__ void __launch_bounds__(256)
gemm128(const float* __restrict__ A, const float* __restrict__ W,
        const float* __restrict__ bias, float* __restrict__ C,
        int M, int K) {
    __shared__ float sA[GBK][GBM];
    __shared__ float sW[GBK][GBN];
    const int tid = threadIdx.x;
    const int tr = tid >> 4;
    const int tc = tid & 15;
    const int bm0 = blockIdx.x * GBM;

    float acc[8][8];
#pragma unroll
    for (int i = 0; i < 8; i++)
#pragma unroll
        for (int j = 0; j < 8; j++) acc[i][j] = 0.f;

    const int ar = tid >> 1;
    const int ak = (tid & 1) * 8;
    const int wr = tid >> 4;
    const int wc = (tid & 15) * 8;

    for (int k0 = 0; k0 < K; k0 += GBK) {
        float4 a0 = make_float4(0.f, 0.f, 0.f, 0.f), a1 = a0;
        int arow = bm0 + ar;
        if (arow < M) {
            const float* ap = &A[(size_t)arow * K + k0 + ak];
            a0 = *reinterpret_cast<const float4*>(ap);
            a1 = *reinterpret_cast<const float4*>(ap + 4);
        }
        sA[ak + 0][ar] = a0.x; sA[ak + 1][ar] = a0.y;
        sA[ak + 2][ar] = a0.z; sA[ak + 3][ar] = a0.w;
        sA[ak + 4][ar] = a1.x; sA[ak + 5][ar] = a1.y;
        sA[ak + 6][ar] = a1.z; sA[ak + 7][ar] = a1.w;
        const float* wp = &W[(size_t)(k0 + wr) * GBN + wc];
        *reinterpret_cast<float4*>(&sW[wr][wc])     = *reinterpret_cast<const float4*>(wp);
        *reinterpret_cast<float4*>(&sW[wr][wc + 4]) = *reinterpret_cast<const float4*>(wp + 4);
        __syncthreads();
#pragma unroll
        for (int k = 0; k < GBK; k++) {
            float4 ra0 = *reinterpret_cast<const float4*>(&sA[k][tr * 8]);
            float4 ra1 = *reinterpret_cast<const float4*>(&sA[k][tr * 8 + 4]);
            float4 rw0 = *reinterpret_cast<const float4*>(&sW[k][tc * 4]);
            float4 rw1 = *reinterpret_cast<const float4*>(&sW[k][64 + tc * 4]);
            float ra[8] = {ra0.x, ra0.y, ra0.z, ra0.w, ra1.x, ra1.y, ra1.z, ra1.w};
            float rw[8] = {rw0.x, rw0.y, rw0.z, rw0.w, rw1.x, rw1.y, rw1.z, rw1.w};
#pragma unroll
            for (int m = 0; m < 8; m++)
#pragma unroll
                for (int n = 0; n < 8; n++) acc[m][n] += ra[m] * rw[n];
        }
        __syncthreads();
    }

    float4 bv0 = make_float4(0.f, 0.f, 0.f, 0.f), bv1 = bv0;
    if (bias) {
        bv0 = *reinterpret_cast<const float4*>(&bias[tc * 4]);
        bv1 = *reinterpret_cast<const float4*>(&bias[64 + tc * 4]);
    }
#pragma unroll
    for (int m = 0; m < 8; m++) {
        int row = bm0 + tr * 8 + m;
        if (row < M) {
            float4 v0 = make_float4(acc[m][0] + bv0.x, acc[m][1] + bv0.y,
                                    acc[m][2] + bv0.z, acc[m][3] + bv0.w);
            float4 v1 = make_float4(acc[m][4] + bv1.x, acc[m][5] + bv1.y,
                                    acc[m][6] + bv1.z, acc[m][7] + bv1.w);
            *reinterpret_cast<float4*>(&C[(size_t)row * GBN + tc * 4]) = v0;
            *reinterpret_cast<float4*>(&C[(size_t)row * GBN + 64 + tc * 4]) = v1;
        }
    }
}

// ---------------- split-bf16 tensor-core GEMM ----------------
// C[M,N] = (Ah+Al)[M,K] @ (Bh+Bl)^T where B is stored n-major [N][K].
// mma.sync.m16n8k16 bf16, fp32 accum, 3-product split (hi*hi + hi*lo + lo*hi).
// Block tile 128x128x32, 256 threads = 8 warps (4M x 2N), warp tile 32x64.
#define SPAD 40   // padded k-row length (bf16) for conflict-free fragment loads

__device__ __forceinline__ void mma16816(float* d, const unsigned* a,
                                         unsigned b0, unsigned b1) {
    asm volatile(
        "mma.sync.aligned.m16n8k16.row.col.f32.bf16.bf16.f32 "
        "{%0,%1,%2,%3}, {%4,%5,%6,%7}, {%8,%9}, {%0,%1,%2,%3};\n"
        : "+f"(d[0]), "+f"(d[1]), "+f"(d[2]), "+f"(d[3])
        : "r"(a[0]), "r"(a[1]), "r"(a[2]), "r"(a[3]), "r"(b0), "r"(b1));
}

__global__ void __launch_bounds__(256)
gemm_mma(const __nv_bfloat16* __restrict__ Ah, const __nv_bfloat16* __restrict__ Al,
         const __nv_bfloat16* __restrict__ Bh, const __nv_bfloat16* __restrict__ Bl,
         float* __restrict__ C, int M, int K, int N) {
    __shared__ __align__(16) __nv_bfloat16 sAh[128 * SPAD];
    __shared__ __align__(16) __nv_bfloat16 sAl[128 * SPAD];
    __shared__ __align__(16) __nv_bfloat16 sBh[128 * SPAD];
    __shared__ __align__(16) __nv_bfloat16 sBl[128 * SPAD];

    const int tid = threadIdx.x;
    const int wid = tid >> 5, lane = tid & 31;
    const int g = lane >> 2, tk = (lane & 3) * 2;
    const int mbase = (wid & 3) * 32, nbase = (wid >> 2) * 64;
    const int bm0 = blockIdx.x * 128, bn0 = blockIdx.y * 128;

    float acc[2][8][4];
#pragma unroll
    for (int a = 0; a < 2; a++)
#pragma unroll
        for (int b = 0; b < 8; b++)
#pragma unroll
            for (int c = 0; c < 4; c++) acc[a][b][c] = 0.f;

    const int lr = tid >> 1;            // tile row 0..127
    const int lk = (tid & 1) * 16;      // k offset 0/16

    for (int k0 = 0; k0 < K; k0 += 32) {
        uint4 z = make_uint4(0, 0, 0, 0);
        uint4 ah0 = z, ah1 = z, al0 = z, al1 = z;
        int gm = bm0 + lr;
        if (gm < M) {
            const uint4* ph = reinterpret_cast<const uint4*>(&Ah[(size_t)gm * K + k0 + lk]);
            const uint4* pl = reinterpret_cast<const uint4*>(&Al[(size_t)gm * K + k0 + lk]);
            ah0 = ph[0]; ah1 = ph[1]; al0 = pl[0]; al1 = pl[1];
        }
        *reinterpret_cast<uint4*>(&sAh[lr * SPAD + lk])     = ah0;
        *reinterpret_cast<uint4*>(&sAh[lr * SPAD + lk + 8]) = ah1;
        *reinterpret_cast<uint4*>(&sAl[lr * SPAD + lk])     = al0;
        *reinterpret_cast<uint4*>(&sAl[lr * SPAD + lk + 8]) = al1;
        {
            const uint4* ph = reinterpret_cast<const uint4*>(&Bh[(size_t)(bn0 + lr) * K + k0 + lk]);
            const uint4* pl = reinterpret_cast<const uint4*>(&Bl[(size_t)(bn0 + lr) * K + k0 + lk]);
            uint4 bh0 = ph[0], bh1 = ph[1], bl0 = pl[0], bl1 = pl[1];
            *reinterpret_cast<uint4*>(&sBh[lr * SPAD + lk])     = bh0;
            *reinterpret_cast<uint4*>(&sBh[lr * SPAD + lk + 8]) = bh1;
            *reinterpret_cast<uint4*>(&sBl[lr * SPAD + lk])     = bl0;
            *reinterpret_cast<uint4*>(&sBl[lr * SPAD + lk + 8]) = bl1;
        }
        __syncthreads();

#pragma unroll
        for (int kk = 0; kk < 32; kk += 16) {
            unsigned fah[2][4], fal[2][4];
#pragma unroll
            for (int ms = 0; ms < 2; ms++) {
                int mr = mbase + ms * 16 + g;
                fah[ms][0] = *reinterpret_cast<const unsigned*>(&sAh[mr * SPAD + kk + tk]);
                fah[ms][1] = *reinterpret_cast<const unsigned*>(&sAh[(mr + 8) * SPAD + kk + tk]);
                fah[ms][2] = *reinterpret_cast<const unsigned*>(&sAh[mr * SPAD + kk + tk + 8]);
                fah[ms][3] = *reinterpret_cast<const unsigned*>(&sAh[(mr + 8) * SPAD + kk + tk + 8]);
                fal[ms][0] = *reinterpret_cast<const unsigned*>(&sAl[mr * SPAD + kk + tk]);
                fal[ms][1] = *reinterpret_cast<const unsigned*>(&sAl[(mr + 8) * SPAD + kk + tk]);
                fal[ms][2] = *reinterpret_cast<const unsigned*>(&sAl[mr * SPAD + kk + tk + 8]);
                fal[ms][3] = *reinterpret_cast<const unsigned*>(&sAl[(mr + 8) * SPAD + kk + tk + 8]);
            }
#pragma unroll
            for (int ns = 0; ns < 8; ns++) {
                int nr = nbase + ns * 8 + g;
                unsigned bh0 = *reinterpret_cast<const unsigned*>(&sBh[nr * SPAD + kk + tk]);
                unsigned bh1 = *reinterpret_cast<const unsigned*>(&sBh[nr * SPAD + kk + tk + 8]);
                unsigned bl0 = *reinterpret_cast<const unsigned*>(&sBl[nr * SPAD + kk + tk]);
                unsigned bl1 = *reinterpret_cast<const unsigned*>(&sBl[nr * SPAD + kk + tk + 8]);
#pragma unroll
                for (int ms = 0; ms < 2; ms++) {
                    mma16816(acc[ms][ns], fah[ms], bh0, bh1);
                    mma16816(acc[ms][ns], fah[ms], bl0, bl1);
                    mma16816(acc[ms][ns], fal[ms], bh0, bh1);
                }
            }
        }
        __syncthreads();
    }

#pragma unroll
    for (int ms = 0; ms < 2; ms++) {
#pragma unroll
        for (int ns = 0; ns < 8; ns++) {
            int row = bm0 + mbase + ms * 16 + g;
            int col = bn0 + nbase + ns * 8 + tk;
            if (row < M)
                *reinterpret_cast<float2*>(&C[(size_t)row * N + col]) =
                    make_float2(acc[ms][ns][0], acc[ms][ns][1]);
            if (row + 8 < M)
                *reinterpret_cast<float2*>(&C[(size_t)(row + 8) * N + col]) =
                    make_float2(acc[ms][ns][2], acc[ms][ns][3]);
        }
    }
}

// ---------------- Wcat conversion: Wol rows [128:1664) -> n-major bf16 hi/lo ----------------
// g_Wch[n][k] = hi(Wol[128 + (n>>7)*512 + k][n&127]), n in [0,384), k in [0,512)
__global__ void conv_wcat() {
    int idx = blockIdx.x * 256 + threadIdx.x;   // 384*512 = 196608, exact grid
    int k = idx & 511;
    int n = idx >> 9;
    int j = n >> 7, c = n & 127;
    float v = g_Wol[(size_t)(128 + j * 512 + k) * HD + c];
    __nv_bfloat16 hh = __float2bfloat16(v);
    g_Wch[(size_t)n * 512 + k] = hh;
    g_Wcl[(size_t)n * 512 + k] = __float2bfloat16(v - __bfloat162float(hh));
}

// ---------------- CSR construction ----------------
__global__ void deg_kernel(const int* __restrict__ dst) {
    int e = blockIdx.x * 256 + threadIdx.x;
    if (e < NE) atomicAdd(&g_deg[dst[e]], 1);
}

__global__ void scan_kernel() {           // single block, 1024 threads
    __shared__ int part[1024];
    const int t = threadIdx.x;
    const int C = (NN + 1023) / 1024;
    int s = 0;
    for (int j = 0; j < C; j++) {
        int i = t * C + j;
        if (i < NN) s += g_deg[i];
    }
    part[t] = s;
    __syncthreads();
    for (int off = 1; off < 1024; off <<= 1) {
        int v = (t >= off) ? part[t - off] : 0;
        __syncthreads();
        part[t] += v;
        __syncthreads();
    }
    int base = t ? part[t - 1] : 0;
    for (int j = 0; j < C; j++) {
        int i = t * C + j;
        if (i < NN) { g_rowptr[i] = base; g_cursor[i] = base; base += g_deg[i]; }
    }
    if (t == 0) g_rowptr[NN] = NE;
}

__global__ void scatter_kernel(const int* __restrict__ dst) {
    int e = blockIdx.x * 256 + threadIdx.x;
    if (e < NE) {
        int p = atomicAdd(&g_cursor[dst[e]], 1);
        g_csr[p] = e;
    }
}

__global__ void permute_kernel(const float* __restrict__ ea,
                               const int* __restrict__ src) {
    int idx = blockIdx.x * 256 + threadIdx.x;   // NE*4 threads
    if (idx < NE * 4) {
        int p = idx >> 2, q = idx & 3;
        int e = g_csr[p];
        reinterpret_cast<float4*>(g_ea2)[p * 4 + q] =
            reinterpret_cast<const float4*>(ea)[e * 4 + q];
        if (q == 0) g_src2[p] = src[e];
    }
}

// ---------------- fold helpers ----------------
__global__ void fold_bias(const float* __restrict__ bv, const float* __restrict__ W,
                          const float* __restrict__ badd, float* __restrict__ out) {
    int c = threadIdx.x;
    float s = badd[c];
    for (int k = 0; k < HD; k++) s += bv[k] * W[k * HD + c];
    out[c] = s;
}

// ---------------- fused edge-message + aggregation ----------------
// Writes agg (bf16 hi/lo split, [N,512] = [mean|min|max|std]) and amp/iamp.
__global__ void __launch_bounds__(128)
agg_fused() {
    const int i = blockIdx.x;
    const int c = threadIdx.x;
    const int beg = g_rowptr[i];
    const int end = g_rowptr[i + 1];
    const int deg = end - beg;

    float wf[IN_EDGE];
#pragma unroll
    for (int k = 0; k < IN_EDGE; k++) wf[k] = g_Wf[k * HD + c];
    const float bfc = g_bf[c];
    const float a = g_A[(size_t)i * HD + c];

    float sum = 0.f, sq = 0.f;
    float mn = 3.4e38f, mx = -3.4e38f;
    int p = beg;
    for (; p + 1 < end; p += 2) {
        int s0 = g_src2[p];
        int s1 = g_src2[p + 1];
        const float4* ea0 = reinterpret_cast<const float4*>(&g_ea2[(size_t)p * IN_EDGE]);
        const float4* ea1 = reinterpret_cast<const float4*>(&g_ea2[(size_t)(p + 1) * IN_EDGE]);
        float4 x0 = ea0[0], x1 = ea0[1], x2 = ea0[2], x3 = ea0[3];
        float4 y0 = ea1[0], y1 = ea1[1], y2 = ea1[2], y3 = ea1[3];
        float b0 = g_B[(size_t)s0 * HD + c];
        float b1 = g_B[(size_t)s1 * HD + c];

        float v0 = bfc + b0;
        v0 += x0.x * wf[0]  + x0.y * wf[1]  + x0.z * wf[2]  + x0.w * wf[3];
        v0 += x1.x * wf[4]  + x1.y * wf[5]  + x1.z * wf[6]  + x1.w * wf[7];
        v0 += x2.x * wf[8]  + x2.y * wf[9]  + x2.z * wf[10] + x2.w * wf[11];
        v0 += x3.x * wf[12] + x3.y * wf[13] + x3.z * wf[14] + x3.w * wf[15];

        float v1 = bfc + b1;
        v1 += y0.x * wf[0]  + y0.y * wf[1]  + y0.z * wf[2]  + y0.w * wf[3];
        v1 += y1.x * wf[4]  + y1.y * wf[5]  + y1.z * wf[6]  + y1.w * wf[7];
        v1 += y2.x * wf[8]  + y2.y * wf[9]  + y2.z * wf[10] + y2.w * wf[11];
        v1 += y3.x * wf[12] + y3.y * wf[13] + y3.z * wf[14] + y3.w * wf[15];

        sum += v0 + v1;
        sq  += v0 * v0 + v1 * v1;
        mn = fminf(mn, fminf(v0, v1));
        mx = fmaxf(mx, fmaxf(v0, v1));
    }
    if (p < end) {
        const float4* ear = reinterpret_cast<const float4*>(&g_ea2[(size_t)p * IN_EDGE]);
        float4 e0 = ear[0], e1 = ear[1], e2 = ear[2], e3 = ear[3];
        int s = g_src2[p];
        float v = bfc + g_B[(size_t)s * HD + c];
        v += e0.x * wf[0]  + e0.y * wf[1]  + e0.z * wf[2]  + e0.w * wf[3];
        v += e1.x * wf[4]  + e1.y * wf[5]  + e1.z * wf[6]  + e1.w * wf[7];
        v += e2.x * wf[8]  + e2.y * wf[9]  + e2.z * wf[10] + e2.w * wf[11];
        v += e3.x * wf[12] + e3.y * wf[13] + e3.z * wf[14] + e3.w * wf[15];
        sum += v; sq += v * v;
        mn = fminf(mn, v); mx = fmaxf(mx, v);
    }

    float mean, mnv, mxv, stdv;
    float fd = (float)deg;
    float degc = fmaxf(fd, 1.f);
    if (deg == 0) {
        mean = 0.f; mnv = 0.f; mxv = 0.f; stdv = sqrtf(EPS_STD);
    } else {
        float inv = 1.f / fd;
        float sum_m = sum + fd * a;        // fold constant A[dst] back in
        mean = sum_m * inv;
        float sq_m = sq + 2.f * a * sum + fd * a * a;
        float msq = sq_m * inv;
        stdv = sqrtf(fmaxf(msq - mean * mean, 0.f) + EPS_STD);
        mnv = mn + a;
        mxv = mx + a;
    }

    float vals[4] = {mean, mnv, mxv, stdv};
    size_t off = (size_t)i * AGG_COLS;
#pragma unroll
    for (int j = 0; j < 4; j++) {
        float v = vals[j];
        __nv_bfloat16 hh = __float2bfloat16(v);
        g_aggh[off + j * HD + c] = hh;
        g_aggl[off + j * HD + c] = __float2bfloat16(v - __bfloat162float(hh));
    }
    if (c == 0) {
        float amp = logf(degc + 1.f) * (1.f / AVG_LOG);
        g_amp[i] = amp;
        g_iamp[i] = 1.f / amp;
    }
}

// ---------------- combine: t += V1 + amp*V2 + iamp*V3; BN column stats ----------------
__global__ void __launch_bounds__(128)
combine_bn() {
    const int c = threadIdx.x;
    const int r0 = blockIdx.x * 128;
    const int rend = min(r0 + 128, NN);
    float s = 0.f, q = 0.f;
    for (int r = r0; r < rend; r++) {
        float amp = g_amp[r], iamp = g_iamp[r];
        size_t vb = (size_t)r * NCAT;
        float t = g_t[(size_t)r * HD + c] + g_V[vb + c]
                + amp * g_V[vb + HD + c] + iamp * g_V[vb + 2 * HD + c];
        g_t[(size_t)r * HD + c] = t;
        s += t; q += t * t;
    }
    atomicAdd(&g_bn[c], s);
    atomicAdd(&g_bn[HD + c], q);
}

// ---------------- batchnorm apply + relu ----------------
__global__ void bn_apply(const float* __restrict__ srcbuf,
                         const float* __restrict__ gamma,
                         const float* __restrict__ beta) {
    int idx = blockIdx.x * 256 + threadIdx.x;
    int c = idx & (HD - 1);
    float mu = g_bn[c] * (1.f / NN);
    float var = g_bn[HD + c] * (1.f / NN) - mu * mu;
    float sc = gamma[c] * rsqrtf(var + EPS_BN);
    float v = (srcbuf[idx] - mu) * sc + beta[c];
    g_h[idx] = fmaxf(v, 0.f);
}

// ---------------- pool + head ----------------
__global__ void pool_kernel(const int* __restrict__ batch) {
    int i = blockIdx.x;
    int c = threadIdx.x;
    atomicAdd(&g_pool[batch[i] * HD + c], g_h[(size_t)i * HD + c]);
}

__global__ void head_kernel(const float* __restrict__ W1, const float* __restrict__ b1,
                            const float* __restrict__ W2, const float* __restrict__ b2,
                            float* __restrict__ out) {
    int g = blockIdx.x;
    int t = threadIdx.x;
    __shared__ float z[64];
    float s = b1[t];
    for (int k = 0; k < HD; k++) s += g_pool[g * HD + k] * W1[k * 64 + t];
    z[t] = fmaxf(s, 0.f);
    __syncthreads();
    if (t < NOUT) {
        float o = b2[t];
        for (int k = 0; k < 64; k++) o += z[k] * W2[k * NOUT + t];
        out[g * NOUT + t] = o;
    }
}

// ---------------- launch ----------------
extern "C" void kernel_launch(void* const* d_in, const int* in_sizes, int n_in,
                              void* d_out, int out_size) {
    (void)n_in; (void)out_size;
    int ix = 0, iei = 1, ib = 2, iea = 3;
    for (int i = 0; i < 4; i++) {
        switch (in_sizes[i]) {
            case NN * IN_NODE: ix  = i; break;
            case 2 * NE:       iei = i; break;
            case NN:           ib  = i; break;
            case NE * IN_EDGE: iea = i; break;
            default: break;
        }
    }
    const float* x     = (const float*)d_in[ix];
    const int*   eidx  = (const int*)  d_in[iei];
    const int*   batch = (const int*)  d_in[ib];
    const float* ea    = (const float*)d_in[iea];
    const float* nW    = (const float*)d_in[4];
    const float* nb    = (const float*)d_in[5];
    const float* eWm   = (const float*)d_in[6];
    const float* ebv   = (const float*)d_in[7];
    const float* encW  = (const float*)d_in[8];
    const float* encB  = (const float*)d_in[9];
    const float* preW  = (const float*)d_in[10];
    const float* preB  = (const float*)d_in[11];
    const float* postW = (const float*)d_in[12];
    const float* postB = (const float*)d_in[13];
    const float* linW  = (const float*)d_in[14];
    const float* linB  = (const float*)d_in[15];
    const float* bnG   = (const float*)d_in[16];
    const float* bnB   = (const float*)d_in[17];
    const float* h1W   = (const float*)d_in[18];
    const float* h1b   = (const float*)d_in[19];
    const float* h2W   = (const float*)d_in[20];
    const float* h2b   = (const float*)d_in[21];
    float* out = (float*)d_out;

    const int* srcp = eidx;
    const int* dstp = eidx + NE;

    void *p_h, *p_A, *p_B, *p_t, *p_deg, *p_Wec, *p_becT, *p_Wf, *p_bf,
         *p_Wol, *p_bol, *p_bn, *p_pool, *p_aggh, *p_aggl, *p_Wch, *p_Wcl, *p_V;
    cudaGetSymbolAddress(&p_h, g_h);
    cudaGetSymbolAddress(&p_A, g_A);
    cudaGetSymbolAddress(&p_B, g_B);
    cudaGetSymbolAddress(&p_t, g_t);
    cudaGetSymbolAddress(&p_deg, g_deg);
    cudaGetSymbolAddress(&p_Wec, g_Wec);
    cudaGetSymbolAddress(&p_becT, g_becT);
    cudaGetSymbolAddress(&p_Wf, g_Wf);
    cudaGetSymbolAddress(&p_bf, g_bf);
    cudaGetSymbolAddress(&p_Wol, g_Wol);
    cudaGetSymbolAddress(&p_bol, g_bol);
    cudaGetSymbolAddress(&p_bn, g_bn);
    cudaGetSymbolAddress(&p_pool, g_pool);
    cudaGetSymbolAddress(&p_aggh, g_aggh);
    cudaGetSymbolAddress(&p_aggl, g_aggl);
    cudaGetSymbolAddress(&p_Wch, g_Wch);
    cudaGetSymbolAddress(&p_Wcl, g_Wcl);
    cudaGetSymbolAddress(&p_V, g_V);

    // ---- CSR build ----
    cudaMemsetAsync(p_deg, 0, NN * sizeof(int));
    deg_kernel<<<(NE + 255) / 256, 256>>>(dstp);
    scan_kernel<<<1, 1024>>>();
    scatter_kernel<<<(NE + 255) / 256, 256>>>(dstp);
    permute_kernel<<<(NE * 4 + 255) / 256, 256>>>(ea, srcp);

    // ---- node embedding ----
    gemm128<<<(NN + GBM - 1) / GBM, 256>>>(x, nW, nb, (float*)p_h, NN, IN_NODE);

    for (int l = 0; l < NLAYERS; l++) {
        const float* preWl  = preW  + (size_t)l * 3 * HD * HD;
        const float* postWl = postW + (size_t)l * KPOST * HD;
        const float* linWl  = linW  + (size_t)l * HD * HD;

        // Wec = encW @ preW[2H:3H];  becT = encB@preW2 + preB
        gemm128<<<1, 256>>>(encW + (size_t)l * HD * HD, preWl + 2 * HD * HD,
                            nullptr, (float*)p_Wec, HD, HD);
        fold_bias<<<1, HD>>>(encB + l * HD, preWl + 2 * HD * HD, preB + l * HD,
                             (float*)p_becT);
        // Wf = eWm @ Wec;  bf = ebv@Wec + becT
        gemm128<<<1, 256>>>(eWm, (const float*)p_Wec, nullptr, (float*)p_Wf,
                            IN_EDGE, HD);
        fold_bias<<<1, HD>>>(ebv, (const float*)p_Wec, (const float*)p_becT,
                             (float*)p_bf);
        // Wol = postW @ linW;  bol = postB@linW + linB
        gemm128<<<13, 256>>>(postWl, linWl, nullptr, (float*)p_Wol, KPOST, HD);
        fold_bias<<<1, HD>>>(postB + l * HD, linWl, linB + l * HD, (float*)p_bol);
        // Wcat (rows 128:1664 of Wol) -> n-major bf16 hi/lo
        conv_wcat<<<(NCAT * AGG_COLS) / 256, 256>>>();

        // node-side pre-NN parts
        gemm128<<<(NN + GBM - 1) / GBM, 256>>>((const float*)p_h, preWl, nullptr,
                                               (float*)p_A, NN, HD);
        gemm128<<<(NN + GBM - 1) / GBM, 256>>>((const float*)p_h, preWl + HD * HD,
                                               nullptr, (float*)p_B, NN, HD);

        // fused edge-message recompute + aggregation -> aggh/aggl, amp, iamp
        agg_fused<<<NN, HD>>>();

        // V0 = h @ W0 + bol (FFMA, small)
        gemm128<<<(NN + GBM - 1) / GBM, 256>>>((const float*)p_h,
                                               (const float*)p_Wol,
                                               (const float*)p_bol, (float*)p_t,
                                               NN, HD);
        // V = agg @ [W1|W2|W3] via split-bf16 tensor cores
        gemm_mma<<<dim3((NN + 127) / 128, NCAT / 128), 256>>>(
            (const __nv_bfloat16*)p_aggh, (const __nv_bfloat16*)p_aggl,
            (const __nv_bfloat16*)p_Wch,  (const __nv_bfloat16*)p_Wcl,
            (float*)p_V, NN, AGG_COLS, NCAT);

        // combine + BN stats, then normalize + relu
        cudaMemsetAsync(p_bn, 0, 2 * HD * 4);
        combine_bn<<<(NN + 127) / 128, 128>>>();
        bn_apply<<<(NN * HD) / 256, 256>>>((const float*)p_t, bnG + l * HD,
                                           bnB + l * HD);
    }

    // global add pool + MLP head
    cudaMemsetAsync(p_pool, 0, NGRAPH * HD * 4);
    pool_kernel<<<NN, HD>>>(batch);
    head_kernel<<<NGRAPH, 64>>>(h1W, h1b, h2W, h2b, out);
}